// round 17
// baseline (speedup 1.0000x reference)
#include <cuda_runtime.h>
#include <cuda_bf16.h>
#include <cstdint>

#define N_ROWS 16384
#define FEATS  512
#define HID    256
#define CLS    64
#define NITER  10

// ---------------- scratch ----------------
__device__ float g_W[FEATS * CLS];
__device__ float g_bias[CLS];
__device__ float g_Z0[N_ROWS * CLS];
__device__ float g_Zfinal[N_ROWS * CLS];
__device__ __nv_bfloat16 g_ZTb[2][CLS * N_ROWS];            // Z^T [class][node], bf16
// adj bf16 tiled images: [tile(128r)][stage(128k)] -> 128x128 bf16 (32KB), swizzled
__device__ uint32_t g_adjTb[(size_t)N_ROWS * N_ROWS / 2];

__device__ __forceinline__ uint32_t smem_u32_of(const void* p) {
    uint32_t a;
    asm("{ .reg .u64 t; cvta.to.shared.u64 t, %1; cvt.u32.u64 %0, t; }" : "=r"(a) : "l"(p));
    return a;
}
__device__ __forceinline__ void cp_async16(uint32_t smem, const void* gmem) {
    asm volatile("cp.async.cg.shared.global [%0], [%1], 16;\n" :: "r"(smem), "l"(gmem));
}
__device__ __forceinline__ void ldmatrix_x4(uint32_t& r0, uint32_t& r1,
                                            uint32_t& r2, uint32_t& r3, uint32_t a) {
    asm volatile("ldmatrix.sync.aligned.m8n8.x4.shared.b16 {%0,%1,%2,%3}, [%4];\n"
                 : "=r"(r0), "=r"(r1), "=r"(r2), "=r"(r3) : "r"(a));
}
__device__ __forceinline__ void mma_bf16(float c[4], const uint32_t a[4],
                                         uint32_t b0, uint32_t b1) {
    asm volatile(
        "mma.sync.aligned.m16n8k16.row.col.f32.bf16.bf16.f32 "
        "{%0,%1,%2,%3}, {%4,%5,%6,%7}, {%8,%9}, {%0,%1,%2,%3};\n"
        : "+f"(c[0]), "+f"(c[1]), "+f"(c[2]), "+f"(c[3])
        : "r"(a[0]), "r"(a[1]), "r"(a[2]), "r"(a[3]), "r"(b0), "r"(b1));
}

// ---------------- kernel 1: collapse the MLP ----------------
__global__ void fuse_w_kernel(const float* __restrict__ W1, const float* __restrict__ b1,
                              const float* __restrict__ W2, const float* __restrict__ b2) {
    int idx = blockIdx.x * blockDim.x + threadIdx.x;
    if (idx < FEATS * CLS) {
        int f = idx / CLS, c = idx % CLS;
        float s = 0.f;
        #pragma unroll 8
        for (int k = 0; k < HID; k++) s += W1[f * HID + k] * W2[k * CLS + c];
        g_W[idx] = s;
    } else if (idx < FEATS * CLS + CLS) {
        int c = idx - FEATS * CLS;
        float s = b2[c];
        for (int k = 0; k < HID; k++) s += b1[k] * W2[k * CLS + c];
        g_bias[c] = s;
    }
}

// ---------------- kernel 2: Z0 = h @ W + bias ----------------
#define Z0_BM 64
#define Z0_BK 16
__global__ __launch_bounds__(256)
void z0_kernel(const float* __restrict__ h) {
    __shared__ float As[Z0_BM][Z0_BK + 1];
    __shared__ float Bs[Z0_BK][CLS + 1];
    int bm = blockIdx.x * Z0_BM;
    int tx = threadIdx.x % 16, ty = threadIdx.x / 16;
    float acc[4][4];
    #pragma unroll
    for (int i = 0; i < 4; i++)
        #pragma unroll
        for (int j = 0; j < 4; j++) acc[i][j] = 0.f;

    for (int k0 = 0; k0 < FEATS; k0 += Z0_BK) {
        for (int i = threadIdx.x; i < Z0_BM * Z0_BK; i += 256) {
            int r = i / Z0_BK, c = i % Z0_BK;
            As[r][c] = h[(size_t)(bm + r) * FEATS + k0 + c];
        }
        for (int i = threadIdx.x; i < Z0_BK * CLS; i += 256) {
            int r = i / CLS, c = i % CLS;
            Bs[r][c] = g_W[(k0 + r) * CLS + c];
        }
        __syncthreads();
        #pragma unroll
        for (int kk = 0; kk < Z0_BK; kk++) {
            float a[4], b[4];
            #pragma unroll
            for (int i = 0; i < 4; i++) a[i] = As[ty * 4 + i][kk];
            #pragma unroll
            for (int j = 0; j < 4; j++) b[j] = Bs[kk][tx * 4 + j];
            #pragma unroll
            for (int i = 0; i < 4; i++)
                #pragma unroll
                for (int j = 0; j < 4; j++) acc[i][j] += a[i] * b[j];
        }
        __syncthreads();
    }
    #pragma unroll
    for (int i = 0; i < 4; i++)
        #pragma unroll
        for (int j = 0; j < 4; j++) {
            int r = bm + ty * 4 + i, c = tx * 4 + j;
            float y = acc[i][j] + g_bias[c];
            g_Z0[(size_t)r * CLS + c] = y;
            g_ZTb[0][c * N_ROWS + r] = __float2bfloat16_rn(y);
        }
}

// ---------------- kernel 3: repack adj -> bf16 images (read-coalesced) ----------------
// Block (t, s4): rows 0..127 of tile t, stages s4*4..s4*4+3.
// Thread sweep ordered (rl, s_local, gi): consecutive tids read each row's
// 2KB (4 stages x 512B) contiguously. Writes land permuted within 512B rows.
__global__ __launch_bounds__(256)
void repack_kernel(const float* __restrict__ adj) {
    const int t  = blockIdx.x >> 5;
    const int s4 = blockIdx.x & 31;
    const int tid = threadIdx.x;
    #pragma unroll 4
    for (int i = 0; i < 32; i++) {
        int g = tid + i * 256;               // 0..8191 granules (32B in, 16B out)
        int rl = g >> 6;
        int rem = g & 63;
        int s_local = rem >> 4;
        int gi = rem & 15;                   // logical k-granule (8 floats)
        const float4* src = (const float4*)(adj +
            (size_t)(t * 128 + rl) * N_ROWS + (s4 * 4 + s_local) * 128 + gi * 8);
        float4 v0 = src[0], v1 = src[1];
        float f[8] = {v0.x, v0.y, v0.z, v0.w, v1.x, v1.y, v1.z, v1.w};
        uint16_t u[8];
        #pragma unroll
        for (int q = 0; q < 8; q++) {
            __nv_bfloat16 hb = __float2bfloat16_rn(f[q]);
            u[q] = *(uint16_t*)&hb;
        }
        int img = t * 128 + s4 * 4 + s_local;
        int gsw = gi ^ (rl & 7);             // baked swizzle
        *(uint4*)(g_adjTb + (size_t)img * 8192 + rl * 64 + gsw * 4) = *(uint4*)u;
    }
}

// ---------------- kernel 4: propagation (bf16 mma, BM=128, SBK=128) ----------------
#define BM 128
#define SBK 128                // k per stage
#define NST (N_ROWS / SBK)     // 128 stages
#define STAGES 3
#define A_W 8192               // words/stage: 128 rows x 64 words (128 bf16), swizzled
#define B_W 4096               // 64 class-rows x 64 words, swizzled
#define STAGE_W (A_W + B_W)    // 12288 words = 48 KB
#define SMEM_BYTES (STAGES * STAGE_W * 4)   // 147456

__global__ __launch_bounds__(256, 1)
void prop_kernel(int it) {
    const int rb = it & 1, wb = rb ^ 1;
    const __nv_bfloat16* ZTin = g_ZTb[rb];

    extern __shared__ uint32_t sm[];
    const uint32_t smem0 = smem_u32_of(sm);

    const int tid   = threadIdx.x;
    const int lane  = tid & 31;
    const int warp  = tid >> 5;
    const int warpM = warp >> 1;        // 0..3, 32 rows
    const int warpN = warp & 1;         // 0..1, 32 cols
    const int tile  = blockIdx.x;
    const int bm    = tile * BM;
    const int lr    = lane & 7;
    const int lg    = lane >> 3;

    auto load_stage = [&](int s, int st) {
        const uint32_t base = smem0 + (s * STAGE_W) * 4;
        const uint32_t* asrc = g_adjTb + ((size_t)(tile * NST + st)) * 8192;
        #pragma unroll
        for (int j = 0; j < 8; j++) {          // A: 2048 contiguous 16B chunks
            int ch = tid + j * 256;
            cp_async16(base + ch * 16, asrc + ch * 4);
        }
        const int k0 = st * SBK;
        #pragma unroll
        for (int j = 0; j < 4; j++) {          // B: 1024 granules of 8 bf16
            int ch = tid + j * 256;
            int c = ch >> 4, gi = ch & 15;
            cp_async16(base + (A_W + c * 64 + ((gi ^ (c & 7)) << 2)) * 4,
                       ZTin + (size_t)c * N_ROWS + k0 + gi * 8);
        }
        asm volatile("cp.async.commit_group;\n");
    };

    float acc[2][4][4];
    #pragma unroll
    for (int mt = 0; mt < 2; mt++)
        #pragma unroll
        for (int nt = 0; nt < 4; nt++)
            #pragma unroll
            for (int i = 0; i < 4; i++) acc[mt][nt][i] = 0.f;

    load_stage(0, 0);
    load_stage(1, 1);

    const uint32_t a_row0 = warpM * 32 + (lane & 15);        // + mt*16
    const uint32_t a_gadd = lane >> 4;                       // + kglobal*2
    const uint32_t b_row0 = warpN * 32 + (lg >> 1) * 8 + lr; // + ntp*16
    const uint32_t b_gadd = lg & 1;                          // + kglobal*2

    for (int st = 0; st < NST; st++) {
        asm volatile("cp.async.wait_group 1;\n");
        __syncthreads();

        int ns = st + 2;
        if (ns < NST) load_stage(ns % STAGES, ns);
        else          asm volatile("cp.async.commit_group;\n");

        const uint32_t base = smem0 + ((st % STAGES) * STAGE_W) * 4;

        #pragma unroll
        for (int half = 0; half < 4; half++) {       // 4 x 32k, reacc each
            float ctile[2][4][4];
            #pragma unroll
            for (int mt = 0; mt < 2; mt++)
                #pragma unroll
                for (int nt = 0; nt < 4; nt++)
                    #pragma unroll
                    for (int i = 0; i < 4; i++) ctile[mt][nt][i] = 0.f;

            #pragma unroll
            for (int kk2 = 0; kk2 < 2; kk2++) {      // k16 chunks
                const uint32_t kg = half * 2 + kk2;  // 0..7
                uint32_t a[2][4];
                #pragma unroll
                for (int mt = 0; mt < 2; mt++) {
                    uint32_t row = a_row0 + mt * 16;
                    uint32_t gi  = kg * 2 + a_gadd;
                    ldmatrix_x4(a[mt][0], a[mt][1], a[mt][2], a[mt][3],
                                base + (row * 64 + ((gi ^ (row & 7)) << 2)) * 4);
                }
                #pragma unroll
                for (int ntp = 0; ntp < 2; ntp++) {
                    uint32_t n  = b_row0 + ntp * 16;
                    uint32_t gi = kg * 2 + b_gadd;
                    uint32_t b0, b1, b2, b3;
                    ldmatrix_x4(b0, b1, b2, b3,
                                base + (A_W + n * 64 + ((gi ^ (n & 7)) << 2)) * 4);
                    #pragma unroll
                    for (int mt = 0; mt < 2; mt++) {
                        mma_bf16(ctile[mt][ntp * 2],     a[mt], b0, b1);
                        mma_bf16(ctile[mt][ntp * 2 + 1], a[mt], b2, b3);
                    }
                }
            }
            #pragma unroll
            for (int mt = 0; mt < 2; mt++)
                #pragma unroll
                for (int nt = 0; nt < 4; nt++)
                    #pragma unroll
                    for (int i = 0; i < 4; i++) acc[mt][nt][i] += ctile[mt][nt][i];
        }
    }

    // epilogue: y = 0.9*acc + 0.1*Z0 ; ZT bf16 always; fp32 at last iter
    #pragma unroll
    for (int mt = 0; mt < 2; mt++) {
        #pragma unroll
        for (int nt = 0; nt < 4; nt++) {
            int r0 = bm + warpM * 32 + mt * 16 + (lane >> 2);
            int c0 = warpN * 32 + (nt >> 1) * 16 + (nt & 1) * 8 + (lane & 3) * 2;
            #pragma unroll
            for (int i = 0; i < 4; i++) {
                int r = r0 + ((i >= 2) ? 8 : 0);
                int c = c0 + (i & 1);
                size_t idx = (size_t)r * CLS + c;
                float y = 0.9f * acc[mt][nt][i] + 0.1f * g_Z0[idx];
                g_ZTb[wb][c * N_ROWS + r] = __float2bfloat16_rn(y);
                if (it == NITER - 1) g_Zfinal[idx] = y;
            }
        }
    }
}

// ---------------- kernel 5: log_softmax ----------------
__global__ __launch_bounds__(256)
void lsm_kernel(float* __restrict__ out) {
    int row  = blockIdx.x * 8 + (threadIdx.x >> 5);
    int lane = threadIdx.x & 31;
    const float* zr = g_Zfinal + (size_t)row * CLS;
    float v0 = zr[lane], v1 = zr[lane + 32];
    float m = fmaxf(v0, v1);
    #pragma unroll
    for (int o = 16; o > 0; o >>= 1) m = fmaxf(m, __shfl_xor_sync(0xffffffffu, m, o));
    float e = expf(v0 - m) + expf(v1 - m);
    #pragma unroll
    for (int o = 16; o > 0; o >>= 1) e += __shfl_xor_sync(0xffffffffu, e, o);
    float l = m + logf(e);
    out[(size_t)row * CLS + lane]      = v0 - l;
    out[(size_t)row * CLS + lane + 32] = v1 - l;
}

// ---------------- launch ----------------
extern "C" void kernel_launch(void* const* d_in, const int* in_sizes, int n_in,
                              void* d_out, int out_size) {
    const float *h = nullptr, *adj = nullptr, *W1 = nullptr,
                *b1 = nullptr, *W2 = nullptr, *b2 = nullptr;
    for (int i = 0; i < n_in; i++) {
        switch (in_sizes[i]) {
            case N_ROWS * FEATS:  h   = (const float*)d_in[i]; break;
            case 268435456:       adj = (const float*)d_in[i]; break;
            case FEATS * HID:     W1  = (const float*)d_in[i]; break;
            case HID:             b1  = (const float*)d_in[i]; break;
            case HID * CLS:       W2  = (const float*)d_in[i]; break;
            case CLS:             b2  = (const float*)d_in[i]; break;
            default: break;
        }
    }

    cudaFuncSetAttribute(prop_kernel, cudaFuncAttributeMaxDynamicSharedMemorySize,
                         SMEM_BYTES);

    fuse_w_kernel<<<(FEATS * CLS + CLS + 255) / 256, 256>>>(W1, b1, W2, b2);
    z0_kernel<<<N_ROWS / Z0_BM, 256>>>(h);
    repack_kernel<<<(N_ROWS / BM) * 32, 256>>>(adj);   // 4096 blocks: (tile, s4)
    for (int it = 0; it < NITER; it++)
        prop_kernel<<<N_ROWS / BM, 256, SMEM_BYTES>>>(it);
    lsm_kernel<<<N_ROWS / 8, 256>>>((float*)d_out);
}